// round 17
// baseline (speedup 1.0000x reference)
#include <cuda_runtime.h>

#define N 8192
#define NC 148           // persistent CTAs, 1 per SM (148 SMs on B300, 152 on GB300)
#define TPB 256
#define CAP 2880         // keys per smem tile: 2880*16B = 46080 B (static; total smem < 48KB)

__device__ float    g_l[N];
__device__ float    g_ang[N];
__device__ float4   g_keys[N];
__device__ double   g_psum[NC];
__device__ double   g_psq[NC];
__device__ int      g_cnt[NC];
__device__ unsigned g_bar[4];   // monotonic tickets; never reset (wrap-safe compare)

__device__ __forceinline__ float ex2f(float x) {
    float r;
    asm("ex2.approx.ftz.f32 %0, %1;" : "=f"(r) : "f"(x));
    return r;
}

__device__ __forceinline__ int chunk_start(int b) {
    return (int)(((long long)b * N) / NC);
}

// Grid-wide barrier: monotonic ticket counter, idempotent across graph replays.
__device__ __forceinline__ void grid_sync(int k) {
    __syncthreads();
    if (threadIdx.x == 0) {
        __threadfence();
        unsigned ticket = atomicAdd(&g_bar[k], 1u) + 1u;
        unsigned target = ((ticket + NC - 1u) / NC) * NC;  // ceil to multiple of NC
        while ((int)(*(volatile unsigned*)&g_bar[k] - target) < 0) __nanosleep(32);
        __threadfence();
    }
    __syncthreads();
}

__global__ __launch_bounds__(TPB) void fused_kernel(const float* __restrict__ x,
                                                    float* __restrict__ out) {
    __shared__ float4 s_keys[CAP];          // 46080 B
    __shared__ double sh_s[8], sh_q[8];
    __shared__ float  sh_thr;
    __shared__ int    sh_c0, sh_base, sh_M;
    __shared__ int    sh_cnts[NC];

    const int b  = blockIdx.x;
    const int t  = threadIdx.x;
    const int e0 = chunk_start(b);
    const int ec = chunk_start(b + 1) - e0;   // <= 56

    // ---------------- Phase 1: l, angle, per-CTA double partial sums --------
    float li = 0.f, ai = 0.f;
    double s = 0.0, q2 = 0.0;
    if (t < ec) {
        int i = e0 + t;
        float2 xi = ((const float2*)x)[i];
        li = sqrtf(xi.x * xi.x + xi.y * xi.y);
        ai = atan2f(xi.y, xi.x);
        g_l[i] = li;
        g_ang[i] = ai;
        s = (double)li;
        q2 = (double)li * (double)li;
    }
    for (int o = 16; o > 0; o >>= 1) {
        s  += __shfl_down_sync(0xffffffffu, s,  o);
        q2 += __shfl_down_sync(0xffffffffu, q2, o);
    }
    if ((t & 31) == 0) { sh_s[t >> 5] = s; sh_q[t >> 5] = q2; }
    __syncthreads();
    if (t == 0) {
        double S = 0.0, Q = 0.0;
        for (int w = 0; w < 8; w++) { S += sh_s[w]; Q += sh_q[w]; }
        g_psum[b] = S;
        g_psq[b]  = Q;
    }
    grid_sync(0);

    // ---------------- Phase 2: threshold (redundant per CTA) + chunk count --
    if (t < 32) {
        double S = 0.0, Q = 0.0;
        for (int i = t; i < NC; i += 32) { S += g_psum[i]; Q += g_psq[i]; }
        for (int o = 16; o > 0; o >>= 1) {
            S += __shfl_down_sync(0xffffffffu, S, o);
            Q += __shfl_down_sync(0xffffffffu, Q, o);
        }
        if (t == 0) {
            double mean = S / (double)N;
            double var = (Q - (double)N * mean * mean) / (double)(N - 1);
            double sd = sqrt(var > 0.0 ? var : 0.0);
            sh_thr = (float)(mean + 0.1 * sd);
        }
    }
    __syncthreads();
    const float thr = sh_thr;
    const int pred = (t < ec) && (li >= thr);
    int c = __syncthreads_count(pred);
    if (t == 0) g_cnt[b] = c;
    grid_sync(1);

    // ---------------- Phase 3: serial prefix (deterministic) + scatter ------
    if (t < NC) sh_cnts[t] = g_cnt[t];
    __syncthreads();
    if (t == 0) {
        int run = 0;
        for (int i = 0; i < b; i++) run += sh_cnts[i];
        sh_base = run;
        for (int i = b; i < NC; i++) run += sh_cnts[i];
        sh_M = run;
    }
    int rank = 0, c0 = 0;
    if (t < 64) {
        unsigned bal = __ballot_sync(0xffffffffu, pred);
        rank = __popc(bal & ((1u << (t & 31)) - 1u));
        if (t == 0) sh_c0 = __popc(bal);
    }
    __syncthreads();
    c0 = sh_c0;
    if (pred) {
        const float HL2E = 0.5f * 1.4426950408889634f;
        int idx = sh_base + rank + (t >= 32 ? c0 : 0);
        g_keys[idx] = make_float4(li, HL2E * li * li, ai, 0.0f);
    }
    grid_sync(2);
    const int M = sh_M;

    // ---------------- Phase 4: softmax-weighted angle + output --------------
    // 4 lanes per row; lane k covers keys j == k (mod 4). All groups in a warp
    // read the same 4 float4s per step -> LDS broadcast, conflict-free.
    const int row_local = t >> 2;
    const int k = t & 3;
    const bool act = row_local < ec;
    const int row = e0 + row_local;
    float lrow = 0.f, q = 0.f;
    if (act) {
        lrow = g_l[row];
        q = -1.4426950408889634f * lrow;
    }

    float num0 = 0.f, num1 = 0.f, den0 = 0.f, den1 = 0.f;
    for (int t0 = 0; t0 < M; t0 += CAP) {
        int tn = min(CAP, M - t0);
        __syncthreads();
        for (int j = t; j < tn; j += TPB) s_keys[j] = g_keys[t0 + j];
        __syncthreads();
        if (act) {
            int j = k;
            for (; j + 12 < tn; j += 16) {
                float4 a0 = s_keys[j], a1 = s_keys[j + 4];
                float4 a2 = s_keys[j + 8], a3 = s_keys[j + 12];
                float e0v = ex2f(fmaf(q, a0.x, a0.y));
                float e1v = ex2f(fmaf(q, a1.x, a1.y));
                float e2v = ex2f(fmaf(q, a2.x, a2.y));
                float e3v = ex2f(fmaf(q, a3.x, a3.y));
                den0 += e0v; num0 = fmaf(e0v, a0.z, num0);
                den1 += e1v; num1 = fmaf(e1v, a1.z, num1);
                den0 += e2v; num0 = fmaf(e2v, a2.z, num0);
                den1 += e3v; num1 = fmaf(e3v, a3.z, num1);
            }
            for (; j < tn; j += 4) {
                float4 a0 = s_keys[j];
                float e0v = ex2f(fmaf(q, a0.x, a0.y));
                den0 += e0v; num0 = fmaf(e0v, a0.z, num0);
            }
        }
    }
    float num = num0 + num1;
    float den = den0 + den1;
    num += __shfl_xor_sync(0xffffffffu, num, 1);
    den += __shfl_xor_sync(0xffffffffu, den, 1);
    num += __shfl_xor_sync(0xffffffffu, num, 2);
    den += __shfl_xor_sync(0xffffffffu, den, 2);

    if (act && k == 0) {
        float th = num / den;
        float sn, cs;
        sincosf(th, &sn, &cs);
        ((float2*)out)[row] = make_float2(lrow * cs, lrow * sn);
    }
}

extern "C" void kernel_launch(void* const* d_in, const int* in_sizes, int n_in,
                              void* d_out, int out_size) {
    const float* x = (const float*)d_in[0];
    float* out = (float*)d_out;
    fused_kernel<<<NC, TPB>>>(x, out);
}